// round 12
// baseline (speedup 1.0000x reference)
#include <cuda_runtime.h>
#include <cstdint>

#define NODE_CAP 102400   // >= num_nodes (100000)

// Scratch (allocation-free). __device__ globals are zero-initialized at load.
// g_sumexp is ALWAYS left zeroed at the end of each launch (k_rcp re-zeros it)
// so graph replays see a clean accumulator without a memset node.
__device__ float g_sumexp[NODE_CAP];
__device__ float g_rcp[NODE_CAP];

// ---------------- pass 1: atomic sum of exp(e), 16 edges/thread ----------------
__global__ void __launch_bounds__(128)
k_sum(const float* __restrict__ e,
      const int* __restrict__ tgt, int n) {
    int v = blockIdx.x * blockDim.x + threadIdx.x;
    int base = v * 16;
    if (base + 15 < n) {
        // Front-batch all loads (max MLP), then a long uninterrupted RED burst.
        float4 e0 = reinterpret_cast<const float4*>(e)[4 * v];
        float4 e1 = reinterpret_cast<const float4*>(e)[4 * v + 1];
        float4 e2 = reinterpret_cast<const float4*>(e)[4 * v + 2];
        float4 e3 = reinterpret_cast<const float4*>(e)[4 * v + 3];
        int4   t0 = reinterpret_cast<const int4*>(tgt)[4 * v];
        int4   t1 = reinterpret_cast<const int4*>(tgt)[4 * v + 1];
        int4   t2 = reinterpret_cast<const int4*>(tgt)[4 * v + 2];
        int4   t3 = reinterpret_cast<const int4*>(tgt)[4 * v + 3];
        atomicAdd(&g_sumexp[t0.x], __expf(e0.x));
        atomicAdd(&g_sumexp[t0.y], __expf(e0.y));
        atomicAdd(&g_sumexp[t0.z], __expf(e0.z));
        atomicAdd(&g_sumexp[t0.w], __expf(e0.w));
        atomicAdd(&g_sumexp[t1.x], __expf(e1.x));
        atomicAdd(&g_sumexp[t1.y], __expf(e1.y));
        atomicAdd(&g_sumexp[t1.z], __expf(e1.z));
        atomicAdd(&g_sumexp[t1.w], __expf(e1.w));
        atomicAdd(&g_sumexp[t2.x], __expf(e2.x));
        atomicAdd(&g_sumexp[t2.y], __expf(e2.y));
        atomicAdd(&g_sumexp[t2.z], __expf(e2.z));
        atomicAdd(&g_sumexp[t2.w], __expf(e2.w));
        atomicAdd(&g_sumexp[t3.x], __expf(e3.x));
        atomicAdd(&g_sumexp[t3.y], __expf(e3.y));
        atomicAdd(&g_sumexp[t3.z], __expf(e3.z));
        atomicAdd(&g_sumexp[t3.w], __expf(e3.w));
    } else {
        for (int i = base; i < n; i++)
            atomicAdd(&g_sumexp[tgt[i]], __expf(e[i]));
    }
}

// ---------------- pass 2: rcp into g_rcp, re-zero accumulator ----------------
__global__ void k_rcp() {
    int i = blockIdx.x * blockDim.x + threadIdx.x;
    if (i < NODE_CAP) {
        g_rcp[i] = 1.0f / (g_sumexp[i] + 1e-16f);
        g_sumexp[i] = 0.0f;   // clean for next graph replay
    }
}

// ---------------- pass 3: alpha = exp(e) * rcp[t], 8 edges/thread ----------------
__global__ void k_norm(const float* __restrict__ e,
                       const int* __restrict__ tgt,
                       float* __restrict__ out, int n) {
    int v = blockIdx.x * blockDim.x + threadIdx.x;
    int base = v * 8;
    if (base + 7 < n) {
        // Last-use streaming reads: evict-first keeps the rcp table hot in L2.
        float4 e0 = __ldcs(&reinterpret_cast<const float4*>(e)[2 * v]);
        float4 e1 = __ldcs(&reinterpret_cast<const float4*>(e)[2 * v + 1]);
        int4   t0 = __ldcs(&reinterpret_cast<const int4*>(tgt)[2 * v]);
        int4   t1 = __ldcs(&reinterpret_cast<const int4*>(tgt)[2 * v + 1]);
        // Batch all gathers first so they overlap in the L1tex queue.
        float r0 = __ldg(&g_rcp[t0.x]);
        float r1 = __ldg(&g_rcp[t0.y]);
        float r2 = __ldg(&g_rcp[t0.z]);
        float r3 = __ldg(&g_rcp[t0.w]);
        float r4 = __ldg(&g_rcp[t1.x]);
        float r5 = __ldg(&g_rcp[t1.y]);
        float r6 = __ldg(&g_rcp[t1.z]);
        float r7 = __ldg(&g_rcp[t1.w]);
        float4 o0, o1;
        o0.x = __expf(e0.x) * r0;
        o0.y = __expf(e0.y) * r1;
        o0.z = __expf(e0.z) * r2;
        o0.w = __expf(e0.w) * r3;
        o1.x = __expf(e1.x) * r4;
        o1.y = __expf(e1.y) * r5;
        o1.z = __expf(e1.z) * r6;
        o1.w = __expf(e1.w) * r7;
        __stcs(&reinterpret_cast<float4*>(out)[2 * v],     o0);
        __stcs(&reinterpret_cast<float4*>(out)[2 * v + 1], o1);
    } else {
        for (int i = base; i < n; i++)
            out[i] = __expf(e[i]) * g_rcp[tgt[i]];
    }
}

extern "C" void kernel_launch(void* const* d_in, const int* in_sizes, int n_in,
                              void* d_out, int out_size) {
    const float* e   = (const float*)d_in[0];
    const int*   ei  = (const int*)d_in[1];   // int32 [2, n]
    float*       out = (float*)d_out;
    int n = in_sizes[0];
    const int* tgt = ei + n;  // row 1 = targets

    const int Ts = 128, Tn = 256;
    int n16 = (n + 15) / 16;
    int n8  = (n + 7) / 8;
    int gs = (n16 + Ts - 1) / Ts;
    int gn = (n8 + Tn - 1) / Tn;
    int gr = (NODE_CAP + Tn - 1) / Tn;

    k_sum <<<gs, Ts>>>(e, tgt, n);
    k_rcp <<<gr, Tn>>>();
    k_norm<<<gn, Tn>>>(e, tgt, out, n);
}

// round 13
// speedup vs baseline: 1.0589x; 1.0589x over previous
#include <cuda_runtime.h>
#include <cstdint>

#define NODE_CAP 102400   // >= num_nodes (100000)

// Scratch (allocation-free). __device__ globals are zero-initialized at load.
// g_sumexp is ALWAYS left zeroed at the end of each launch (k_rcp re-zeros it)
// so graph replays see a clean accumulator without a memset node.
__device__ float g_sumexp[NODE_CAP];
__device__ float g_rcp[NODE_CAP];

// ---------------- pass 1: atomic sum of exp(e), 8 edges/thread, T=512 ----------------
__global__ void k_sum(const float* __restrict__ e,
                      const int* __restrict__ tgt, int n) {
    int v = blockIdx.x * blockDim.x + threadIdx.x;
    int base = v * 8;
    if (base + 7 < n) {
        float4 e0 = reinterpret_cast<const float4*>(e)[2 * v];
        float4 e1 = reinterpret_cast<const float4*>(e)[2 * v + 1];
        int4   t0 = reinterpret_cast<const int4*>(tgt)[2 * v];
        int4   t1 = reinterpret_cast<const int4*>(tgt)[2 * v + 1];
        atomicAdd(&g_sumexp[t0.x], __expf(e0.x));
        atomicAdd(&g_sumexp[t0.y], __expf(e0.y));
        atomicAdd(&g_sumexp[t0.z], __expf(e0.z));
        atomicAdd(&g_sumexp[t0.w], __expf(e0.w));
        atomicAdd(&g_sumexp[t1.x], __expf(e1.x));
        atomicAdd(&g_sumexp[t1.y], __expf(e1.y));
        atomicAdd(&g_sumexp[t1.z], __expf(e1.z));
        atomicAdd(&g_sumexp[t1.w], __expf(e1.w));
    } else {
        for (int i = base; i < n; i++)
            atomicAdd(&g_sumexp[tgt[i]], __expf(e[i]));
    }
}

// ---------------- pass 2: rcp into g_rcp, re-zero accumulator ----------------
__global__ void k_rcp() {
    int i = blockIdx.x * blockDim.x + threadIdx.x;
    if (i < NODE_CAP) {
        g_rcp[i] = 1.0f / (g_sumexp[i] + 1e-16f);
        g_sumexp[i] = 0.0f;   // clean for next graph replay
    }
}

// ---------------- pass 3: alpha = exp(e) * rcp[t], 8 edges/thread, T=256 ----------------
__global__ void k_norm(const float* __restrict__ e,
                       const int* __restrict__ tgt,
                       float* __restrict__ out, int n) {
    int v = blockIdx.x * blockDim.x + threadIdx.x;
    int base = v * 8;
    if (base + 7 < n) {
        // Last-use streaming reads: evict-first keeps the rcp table hot in L2.
        float4 e0 = __ldcs(&reinterpret_cast<const float4*>(e)[2 * v]);
        float4 e1 = __ldcs(&reinterpret_cast<const float4*>(e)[2 * v + 1]);
        int4   t0 = __ldcs(&reinterpret_cast<const int4*>(tgt)[2 * v]);
        int4   t1 = __ldcs(&reinterpret_cast<const int4*>(tgt)[2 * v + 1]);
        // Batch all gathers first so they overlap in the L1tex queue.
        float r0 = __ldg(&g_rcp[t0.x]);
        float r1 = __ldg(&g_rcp[t0.y]);
        float r2 = __ldg(&g_rcp[t0.z]);
        float r3 = __ldg(&g_rcp[t0.w]);
        float r4 = __ldg(&g_rcp[t1.x]);
        float r5 = __ldg(&g_rcp[t1.y]);
        float r6 = __ldg(&g_rcp[t1.z]);
        float r7 = __ldg(&g_rcp[t1.w]);
        float4 o0, o1;
        o0.x = __expf(e0.x) * r0;
        o0.y = __expf(e0.y) * r1;
        o0.z = __expf(e0.z) * r2;
        o0.w = __expf(e0.w) * r3;
        o1.x = __expf(e1.x) * r4;
        o1.y = __expf(e1.y) * r5;
        o1.z = __expf(e1.z) * r6;
        o1.w = __expf(e1.w) * r7;
        __stcs(&reinterpret_cast<float4*>(out)[2 * v],     o0);
        __stcs(&reinterpret_cast<float4*>(out)[2 * v + 1], o1);
    } else {
        for (int i = base; i < n; i++)
            out[i] = __expf(e[i]) * g_rcp[tgt[i]];
    }
}

extern "C" void kernel_launch(void* const* d_in, const int* in_sizes, int n_in,
                              void* d_out, int out_size) {
    const float* e   = (const float*)d_in[0];
    const int*   ei  = (const int*)d_in[1];   // int32 [2, n]
    float*       out = (float*)d_out;
    int n = in_sizes[0];
    const int* tgt = ei + n;  // row 1 = targets

    int nv = (n + 7) / 8;
    const int Ts = 512, Tn = 256;
    int gs = (nv + Ts - 1) / Ts;
    int gn = (nv + Tn - 1) / Tn;
    int gr = (NODE_CAP + Tn - 1) / Tn;

    k_sum <<<gs, Ts>>>(e, tgt, n);
    k_rcp <<<gr, Tn>>>();
    k_norm<<<gn, Tn>>>(e, tgt, out, n);
}